// round 1
// baseline (speedup 1.0000x reference)
#include <cuda_runtime.h>
#include <math.h>

#define DM   768
#define DI   1536
#define NS   16
#define DR   48
#define NB   2
#define LSEQ 1024
#define NT   (NB*LSEQ)      // 2048 tokens
#define XZW  (2*DI)         // 3072

// ---------------- scratch (static device memory; no allocations) ----------
__device__ float g_x0[NT*DM];          // layernorm output
__device__ float g_xz[2][NT*XZW];      // in_proj output per dir (xc | z)
__device__ float g_xc[2][NT*DI];       // conv+silu output per dir
__device__ float g_dbc[2][NT*80];      // xproj output (dt|B|C)
__device__ float g_delta[2][NT*DI];    // softplus(dt @ dt_w.T + dt_b)
__device__ float g_y[2][NT*DI];        // scan output (gated)

__device__ __forceinline__ float silu_(float v){ return v / (1.f + __expf(-v)); }
__device__ __forceinline__ float softplus_(float v){
    return (v > 20.f) ? v : log1pf(__expf(v));
}

// ---------------- 1) LayerNorm --------------------------------------------
__global__ void k_ln(const float* __restrict__ x, const float* __restrict__ g,
                     const float* __restrict__ b)
{
    int t = blockIdx.x;
    const float* xr = x + (size_t)t*DM;
    float s = 0.f, s2 = 0.f;
    for (int i = threadIdx.x; i < DM; i += 256) { float v = xr[i]; s += v; s2 += v*v; }
    #pragma unroll
    for (int o = 16; o > 0; o >>= 1) {
        s  += __shfl_xor_sync(0xffffffffu, s,  o);
        s2 += __shfl_xor_sync(0xffffffffu, s2, o);
    }
    __shared__ float sh[16];
    int w = threadIdx.x >> 5, l = threadIdx.x & 31;
    if (l == 0) { sh[w] = s; sh[w+8] = s2; }
    __syncthreads();
    float S = 0.f, S2 = 0.f;
    #pragma unroll
    for (int i = 0; i < 8; i++) { S += sh[i]; S2 += sh[i+8]; }
    float mean = S / DM;
    float inv  = rsqrtf(S2 / DM - mean*mean + 1e-5f);
    for (int i = threadIdx.x; i < DM; i += 256)
        g_x0[(size_t)t*DM + i] = (xr[i] - mean)*inv*g[i] + b[i];
}

// ---------------- 2) in_proj GEMM: xz[dir] = x0 @ in_w[dir]^T -------------
// A: 2048x768 row-major (K contig), W: 3072x768 row-major (K contig)
__launch_bounds__(256, 2)
__global__ void k_gemm_in(const float* __restrict__ wf, const float* __restrict__ wb)
{
    const int K = DM, N = XZW;
    int dir = blockIdx.z;
    const float* A  = g_x0;
    const float* Bw = dir ? wb : wf;
    float* C = g_xz[dir];

    int m0 = blockIdx.y * 128, n0 = blockIdx.x * 128;
    __shared__ float As[8][128];
    __shared__ float Bs[8][128];

    int tid = threadIdx.x;
    int lr = tid >> 1, lk = (tid & 1) * 4;
    const float* Ag = A  + (size_t)(m0 + lr)*K + lk;
    const float* Bg = Bw + (size_t)(n0 + lr)*K + lk;

    int ty = tid >> 4, tx = tid & 15;
    float acc[8][8] = {};

    for (int k0 = 0; k0 < K; k0 += 8) {
        float4 av = *(const float4*)(Ag + k0);
        float4 bv = *(const float4*)(Bg + k0);
        __syncthreads();
        As[lk+0][lr] = av.x; As[lk+1][lr] = av.y; As[lk+2][lr] = av.z; As[lk+3][lr] = av.w;
        Bs[lk+0][lr] = bv.x; Bs[lk+1][lr] = bv.y; Bs[lk+2][lr] = bv.z; Bs[lk+3][lr] = bv.w;
        __syncthreads();
        #pragma unroll
        for (int kk = 0; kk < 8; kk++) {
            float a[8], bb[8];
            *(float4*)(a)    = *(const float4*)&As[kk][ty*8];
            *(float4*)(a+4)  = *(const float4*)&As[kk][ty*8+4];
            *(float4*)(bb)   = *(const float4*)&Bs[kk][tx*8];
            *(float4*)(bb+4) = *(const float4*)&Bs[kk][tx*8+4];
            #pragma unroll
            for (int i = 0; i < 8; i++)
                #pragma unroll
                for (int j = 0; j < 8; j++)
                    acc[i][j] = fmaf(a[i], bb[j], acc[i][j]);
        }
    }
    #pragma unroll
    for (int i = 0; i < 8; i++) {
        float* cp = C + (size_t)(m0 + ty*8 + i)*N + n0 + tx*8;
        *(float4*)(cp)   = make_float4(acc[i][0], acc[i][1], acc[i][2], acc[i][3]);
        *(float4*)(cp+4) = make_float4(acc[i][4], acc[i][5], acc[i][6], acc[i][7]);
    }
}

// ---------------- 3) depthwise conv + bias + SiLU -------------------------
// fwd: y[s] = w0*x[s-3]+w1*x[s-2]+w2*x[s-1]+w3*x[s]
// bwd (flip-equivalent in original order): y[s] = w3*x[s]+w2*x[s+1]+w1*x[s+2]+w0*x[s+3]
__global__ void k_conv(const float* __restrict__ cwf, const float* __restrict__ cbf,
                       const float* __restrict__ cwb, const float* __restrict__ cbb)
{
    int d   = blockIdx.x * 256 + threadIdx.x;   // < 1536
    int s0  = blockIdx.y * 64;
    int dir = blockIdx.z >> 1, b = blockIdx.z & 1;
    const float* cw = dir ? cwb : cwf;
    float bias = (dir ? cbb : cbf)[d];
    float w0 = cw[d*4+0], w1 = cw[d*4+1], w2 = cw[d*4+2], w3 = cw[d*4+3];

    const float* xin  = g_xz[dir] + (size_t)b*LSEQ*XZW + d;
    float*       xout = g_xc[dir] + (size_t)b*LSEQ*DI  + d;

    if (dir == 0) {
        float xm3 = (s0 >= 3) ? xin[(size_t)(s0-3)*XZW] : 0.f;
        float xm2 = (s0 >= 2) ? xin[(size_t)(s0-2)*XZW] : 0.f;
        float xm1 = (s0 >= 1) ? xin[(size_t)(s0-1)*XZW] : 0.f;
        for (int i = 0; i < 64; i++) {
            int s = s0 + i;
            float x0 = xin[(size_t)s*XZW];
            float v = fmaf(w0, xm3, fmaf(w1, xm2, fmaf(w2, xm1, fmaf(w3, x0, bias))));
            xout[(size_t)s*DI] = silu_(v);
            xm3 = xm2; xm2 = xm1; xm1 = x0;
        }
    } else {
        float a0 = xin[(size_t)s0*XZW];
        float a1 = (s0+1 < LSEQ) ? xin[(size_t)(s0+1)*XZW] : 0.f;
        float a2 = (s0+2 < LSEQ) ? xin[(size_t)(s0+2)*XZW] : 0.f;
        for (int i = 0; i < 64; i++) {
            int s = s0 + i;
            float a3 = (s+3 < LSEQ) ? xin[(size_t)(s+3)*XZW] : 0.f;
            float v = fmaf(w3, a0, fmaf(w2, a1, fmaf(w1, a2, fmaf(w0, a3, bias))));
            xout[(size_t)s*DI] = silu_(v);
            a0 = a1; a1 = a2; a2 = a3;
        }
    }
}

// ---------------- 4) xproj: dbc = xc @ xproj_w^T  (N=80, K=1536) ----------
__global__ void k_xproj(const float* __restrict__ xwf, const float* __restrict__ xwb)
{
    int dir = blockIdx.z;
    int t0  = blockIdx.x * 32;
    const float* xw = dir ? xwb : xwf;
    const float* X  = g_xc[dir];

    __shared__ float Xs[32][33];
    __shared__ float Ws[80][33];

    int tid = threadIdx.x;
    int tm = tid >> 4, tn = tid & 15;
    float acc[2][5] = {};

    for (int k0 = 0; k0 < DI; k0 += 32) {
        int m = tid >> 5, k = tid & 31;
        #pragma unroll
        for (int r = 0; r < 4; r++)
            Xs[m + r*8][k] = X[(size_t)(t0 + m + r*8)*DI + k0 + k];
        #pragma unroll
        for (int r = 0; r < 10; r++)
            Ws[m + r*8][k] = xw[(size_t)(m + r*8)*DI + k0 + k];
        __syncthreads();
        #pragma unroll
        for (int k2 = 0; k2 < 32; k2++) {
            float a0 = Xs[tm*2][k2], a1 = Xs[tm*2+1][k2];
            #pragma unroll
            for (int j = 0; j < 5; j++) {
                float wv = Ws[tn*5 + j][k2];
                acc[0][j] = fmaf(a0, wv, acc[0][j]);
                acc[1][j] = fmaf(a1, wv, acc[1][j]);
            }
        }
        __syncthreads();
    }
    #pragma unroll
    for (int i = 0; i < 2; i++)
        #pragma unroll
        for (int j = 0; j < 5; j++)
            g_dbc[dir][(size_t)(t0 + tm*2 + i)*80 + tn*5 + j] = acc[i][j];
}

// ---------------- 5) delta: softplus(dt @ dt_w^T + dt_b) (K=48) -----------
__global__ void k_delta(const float* __restrict__ dtwf, const float* __restrict__ dtbf,
                        const float* __restrict__ dtwb, const float* __restrict__ dtbb)
{
    int dir = blockIdx.z;
    int d   = blockIdx.x * 256 + threadIdx.x;  // grid.x = 6
    int t0  = blockIdx.y * 16;                 // grid.y = 128
    const float* dtw = dir ? dtwb : dtwf;
    float bias = (dir ? dtbb : dtbf)[d];

    float4 w[12];
    const float4* wr = (const float4*)(dtw + (size_t)d*48);
    #pragma unroll
    for (int i = 0; i < 12; i++) w[i] = wr[i];

    __shared__ float4 Ds[16][12];
    if (threadIdx.x < 192) {
        int t = threadIdx.x / 12, q = threadIdx.x % 12;
        Ds[t][q] = *(const float4*)(g_dbc[dir] + (size_t)(t0 + t)*80 + q*4);
    }
    __syncthreads();

    #pragma unroll 4
    for (int t = 0; t < 16; t++) {
        float acc = bias;
        #pragma unroll
        for (int q = 0; q < 12; q++) {
            float4 a = Ds[t][q];
            acc = fmaf(a.x, w[q].x, acc);
            acc = fmaf(a.y, w[q].y, acc);
            acc = fmaf(a.z, w[q].z, acc);
            acc = fmaf(a.w, w[q].w, acc);
        }
        g_delta[dir][(size_t)(t0 + t)*DI + d] = softplus_(acc);
    }
}

// ---------------- 6) selective scan (fwd: s 0->L-1, bwd: s L-1->0) --------
// thread = (d_local, n); block = 16 d x 16 n; h recurrence in registers,
// per-32-step SMEM staging of delta/xc/B/C/z so the recurrence critical path
// is FFMA latency, not DRAM.
__global__ void k_scan(const float* __restrict__ alf, const float* __restrict__ df,
                       const float* __restrict__ alb, const float* __restrict__ db_)
{
    int dir = blockIdx.z, b = blockIdx.y, d0 = blockIdx.x * 16;
    int tid = threadIdx.x, dl = tid >> 4, n = tid & 15, d = d0 + dl;

    const float* al = dir ? alb : alf;
    float Ad = -__expf(al[(size_t)d*NS + n]);
    float Dd = (dir ? db_ : df)[d];

    const float* pdel = g_delta[dir] + (size_t)b*LSEQ*DI;
    const float* pxc  = g_xc[dir]    + (size_t)b*LSEQ*DI;
    const float* pdbc = g_dbc[dir]   + (size_t)b*LSEQ*80;
    const float* pz   = g_xz[dir]    + (size_t)b*LSEQ*XZW + DI;
    float*       py   = g_y[dir]     + (size_t)b*LSEQ*DI;

    __shared__ float sdel[32][16], sxc[32][16], sB[32][16], sC[32][16], sz[32][16];

    float h = 0.f;
    for (int c = 0; c < LSEQ/32; c++) {
        int base = c * 32;
        #pragma unroll
        for (int idx = tid; idx < 512; idx += 256) {
            int i = idx >> 4, dd = idx & 15;
            int s = dir ? (LSEQ - 1 - (base + i)) : (base + i);
            size_t row = (size_t)s;
            sdel[i][dd] = pdel[row*DI  + d0 + dd];
            sxc [i][dd] = pxc [row*DI  + d0 + dd];
            sz  [i][dd] = pz  [row*XZW + d0 + dd];
            sB  [i][dd] = pdbc[row*80 + 48 + dd];
            sC  [i][dd] = pdbc[row*80 + 64 + dd];
        }
        __syncthreads();
        #pragma unroll 4
        for (int i = 0; i < 32; i++) {
            float dv = sdel[i][dl], xv = sxc[i][dl];
            float e  = __expf(dv * Ad);
            float du = dv * xv;
            h = fmaf(e, h, du * sB[i][n]);
            float p = h * sC[i][n];
            p += __shfl_xor_sync(0xffffffffu, p, 1);
            p += __shfl_xor_sync(0xffffffffu, p, 2);
            p += __shfl_xor_sync(0xffffffffu, p, 4);
            p += __shfl_xor_sync(0xffffffffu, p, 8);
            if (n == 0) {
                int s = dir ? (LSEQ - 1 - (base + i)) : (base + i);
                float zv = sz[i][dl];
                py[(size_t)s*DI + d] = (p + xv*Dd) * silu_(zv);
            }
        }
        __syncthreads();
    }
}

// ---------------- 7) out_proj + residual: out = x + y0@W0^T + y1@W1^T ------
__launch_bounds__(256, 2)
__global__ void k_outproj(const float* __restrict__ owf, const float* __restrict__ owb,
                          const float* __restrict__ resid, float* __restrict__ out)
{
    const int K = DI, N = DM;
    int m0 = blockIdx.y * 128, n0 = blockIdx.x * 128;
    __shared__ float As[8][128];
    __shared__ float Bs[8][128];

    int tid = threadIdx.x;
    int lr = tid >> 1, lk = (tid & 1) * 4;
    int ty = tid >> 4, tx = tid & 15;
    float acc[8][8] = {};

    for (int src = 0; src < 2; src++) {
        const float* A  = g_y[src];
        const float* Bw = src ? owb : owf;
        const float* Ag = A  + (size_t)(m0 + lr)*K + lk;
        const float* Bg = Bw + (size_t)(n0 + lr)*K + lk;
        for (int k0 = 0; k0 < K; k0 += 8) {
            float4 av = *(const float4*)(Ag + k0);
            float4 bv = *(const float4*)(Bg + k0);
            __syncthreads();
            As[lk+0][lr] = av.x; As[lk+1][lr] = av.y; As[lk+2][lr] = av.z; As[lk+3][lr] = av.w;
            Bs[lk+0][lr] = bv.x; Bs[lk+1][lr] = bv.y; Bs[lk+2][lr] = bv.z; Bs[lk+3][lr] = bv.w;
            __syncthreads();
            #pragma unroll
            for (int kk = 0; kk < 8; kk++) {
                float a[8], bb[8];
                *(float4*)(a)    = *(const float4*)&As[kk][ty*8];
                *(float4*)(a+4)  = *(const float4*)&As[kk][ty*8+4];
                *(float4*)(bb)   = *(const float4*)&Bs[kk][tx*8];
                *(float4*)(bb+4) = *(const float4*)&Bs[kk][tx*8+4];
                #pragma unroll
                for (int i = 0; i < 8; i++)
                    #pragma unroll
                    for (int j = 0; j < 8; j++)
                        acc[i][j] = fmaf(a[i], bb[j], acc[i][j]);
            }
        }
    }
    #pragma unroll
    for (int i = 0; i < 8; i++) {
        size_t roff = (size_t)(m0 + ty*8 + i)*N + n0 + tx*8;
        const float* rp = resid + roff;
        float* cp = out + roff;
        #pragma unroll
        for (int j = 0; j < 8; j++) cp[j] = acc[i][j] + rp[j];
    }
}

// ---------------- launch ---------------------------------------------------
extern "C" void kernel_launch(void* const* d_in, const int* in_sizes, int n_in,
                              void* d_out, int out_size)
{
    const float* x    = (const float*)d_in[0];
    const float* ln_g = (const float*)d_in[1];
    const float* ln_b = (const float*)d_in[2];
    const float* f_in_w    = (const float*)d_in[3];
    const float* f_conv_w  = (const float*)d_in[4];
    const float* f_conv_b  = (const float*)d_in[5];
    const float* f_xproj_w = (const float*)d_in[6];
    const float* f_dt_w    = (const float*)d_in[7];
    const float* f_dt_b    = (const float*)d_in[8];
    const float* f_A_log   = (const float*)d_in[9];
    const float* f_D       = (const float*)d_in[10];
    const float* f_out_w   = (const float*)d_in[11];
    const float* b_in_w    = (const float*)d_in[12];
    const float* b_conv_w  = (const float*)d_in[13];
    const float* b_conv_b  = (const float*)d_in[14];
    const float* b_xproj_w = (const float*)d_in[15];
    const float* b_dt_w    = (const float*)d_in[16];
    const float* b_dt_b    = (const float*)d_in[17];
    const float* b_A_log   = (const float*)d_in[18];
    const float* b_D       = (const float*)d_in[19];
    const float* b_out_w   = (const float*)d_in[20];
    float* out = (float*)d_out;

    k_ln<<<NT, 256>>>(x, ln_g, ln_b);
    k_gemm_in<<<dim3(XZW/128, NT/128, 2), 256>>>(f_in_w, b_in_w);
    k_conv<<<dim3(DI/256, LSEQ/64, 4), 256>>>(f_conv_w, f_conv_b, b_conv_w, b_conv_b);
    k_xproj<<<dim3(NT/32, 1, 2), 256>>>(f_xproj_w, b_xproj_w);
    k_delta<<<dim3(DI/256, NT/16, 2), 256>>>(f_dt_w, f_dt_b, b_dt_w, b_dt_b);
    k_scan<<<dim3(DI/16, NB, 2), 256>>>(f_A_log, f_D, b_A_log, b_D);
    k_outproj<<<dim3(DM/128, NT/128), 256>>>(f_out_w, b_out_w, x, out);
}

// round 3
// speedup vs baseline: 1.7267x; 1.7267x over previous
#include <cuda_runtime.h>
#include <cuda_fp16.h>
#include <math.h>
#include <stdint.h>

#define DM   768
#define DI   1536
#define NS   16
#define NB   2
#define LSEQ 1024
#define NT   (NB*LSEQ)      // 2048 tokens
#define XZW  (2*DI)         // 3072

// ================= PTX helpers (sm_80-compatible: cp.async / ldmatrix / mma) ==
__device__ __forceinline__ uint32_t smem_u32(const void* p) {
    uint32_t a;
    asm("{ .reg .u64 t; cvta.to.shared.u64 t, %1; cvt.u32.u64 %0, t; }" : "=r"(a) : "l"(p));
    return a;
}
#define CP_ASYNC16(dst, src) \
    asm volatile("cp.async.cg.shared.global [%0], [%1], 16;\n" :: "r"(dst), "l"(src))
#define CP_COMMIT() asm volatile("cp.async.commit_group;\n" ::: "memory")
#define CP_WAIT1()  asm volatile("cp.async.wait_group 1;\n" ::: "memory")
#define CP_WAIT0()  asm volatile("cp.async.wait_group 0;\n" ::: "memory")

__device__ __forceinline__ void ldsm4(uint32_t& r0, uint32_t& r1, uint32_t& r2, uint32_t& r3,
                                      uint32_t addr) {
    asm volatile("ldmatrix.sync.aligned.m8n8.x4.shared.b16 {%0,%1,%2,%3}, [%4];\n"
        : "=r"(r0), "=r"(r1), "=r"(r2), "=r"(r3) : "r"(addr));
}
__device__ __forceinline__ void mma16816(float c[4], uint32_t a0, uint32_t a1, uint32_t a2,
                                         uint32_t a3, uint32_t b0, uint32_t b1) {
    asm volatile("mma.sync.aligned.m16n8k16.row.col.f32.f16.f16.f32 "
        "{%0,%1,%2,%3}, {%4,%5,%6,%7}, {%8,%9}, {%0,%1,%2,%3};\n"
        : "+f"(c[0]), "+f"(c[1]), "+f"(c[2]), "+f"(c[3])
        : "r"(a0), "r"(a1), "r"(a2), "r"(a3), "r"(b0), "r"(b1));
}

// ================= scratch (static device memory) ============================
__device__ float g_xz[2][NT*XZW];        // in_proj output per dir (xc | z)
__device__ float g_xc[2][NT*DI];         // conv+silu output per dir (fp32, for scan)
__device__ float g_dbc[2][NT*80];        // xproj output (dt|B|C)
__device__ float g_delta[2][NT*DI];

// fp16 hi/lo split buffers (16B aligned for cp.async)
__device__ __align__(256) __half g_a0h[NT*DM],   g_a0l[NT*DM];
__device__ __align__(256) __half g_winh[2][XZW*DM], g_winl[2][XZW*DM];
__device__ __align__(256) __half g_wxph[2][128*DI], g_wxpl[2][128*DI];
__device__ __align__(256) __half g_wouth[DM*XZW],   g_woutl[DM*XZW];   // concat [768][3072]
__device__ __align__(256) __half g_axch[2][NT*DI],  g_axcl[2][NT*DI];  // conv output
__device__ __align__(256) __half g_ycath[NT*XZW],   g_ycatl[NT*XZW];   // scan out concat

__device__ __forceinline__ float silu_(float v){ return v / (1.f + __expf(-v)); }
__device__ __forceinline__ float softplus_(float v){ return (v > 20.f) ? v : log1pf(__expf(v)); }
__device__ __forceinline__ void split_f16(float v, __half* h, __half* l){
    __half hh = __float2half_rn(v);
    *h = hh;
    *l = __float2half_rn(v - __half2float(hh));
}

// ================= 1) LayerNorm -> fp16 hi/lo ================================
__global__ void k_ln(const float* __restrict__ x, const float* __restrict__ g,
                     const float* __restrict__ b)
{
    int t = blockIdx.x;
    const float* xr = x + (size_t)t*DM;
    float s = 0.f, s2 = 0.f;
    for (int i = threadIdx.x; i < DM; i += 256) { float v = xr[i]; s += v; s2 += v*v; }
    #pragma unroll
    for (int o = 16; o > 0; o >>= 1) {
        s  += __shfl_xor_sync(0xffffffffu, s,  o);
        s2 += __shfl_xor_sync(0xffffffffu, s2, o);
    }
    __shared__ float sh[16];
    int w = threadIdx.x >> 5, l = threadIdx.x & 31;
    if (l == 0) { sh[w] = s; sh[w+8] = s2; }
    __syncthreads();
    float S = 0.f, S2 = 0.f;
    #pragma unroll
    for (int i = 0; i < 8; i++) { S += sh[i]; S2 += sh[i+8]; }
    float mean = S / DM;
    float inv  = rsqrtf(S2 / DM - mean*mean + 1e-5f);
    for (int i = threadIdx.x; i < DM; i += 256) {
        float v = (xr[i] - mean)*inv*g[i] + b[i];
        split_f16(v, &g_a0h[(size_t)t*DM + i], &g_a0l[(size_t)t*DM + i]);
    }
}

// ================= weight conversion kernels ================================
__global__ void k_cvtw_in(const float* __restrict__ f, const float* __restrict__ b) {
    int dir = blockIdx.z;
    int i = blockIdx.x*256 + threadIdx.x;
    if (i >= XZW*DM) return;
    float v = (dir ? b : f)[i];
    split_f16(v, &g_winh[dir][i], &g_winl[dir][i]);
}
__global__ void k_cvtw_xp(const float* __restrict__ f, const float* __restrict__ b) {
    int dir = blockIdx.z;
    int i = blockIdx.x*256 + threadIdx.x;
    if (i >= 128*DI) return;
    int row = i / DI;
    float v = (row < 80) ? (dir ? b : f)[i] : 0.f;
    split_f16(v, &g_wxph[dir][i], &g_wxpl[dir][i]);
}
__global__ void k_cvtw_out(const float* __restrict__ f, const float* __restrict__ b) {
    int i = blockIdx.x*256 + threadIdx.x;
    if (i >= DM*XZW) return;
    int n = i / XZW, c = i % XZW;
    float v = (c < DI) ? f[(size_t)n*DI + c] : b[(size_t)n*DI + c - DI];
    split_f16(v, &g_wouth[i], &g_woutl[i]);
}

// ================= HMMA GEMM:  C[M,N] = A[M,K] * B[N,K]^T (fp16 split x3) ====
// BM=128, BN=128, BK=64 halves (128B SW128 rows), 8 warps (2x4), warp tile 64x32.
// 3 K-phases: (Ah,Bh), (Al,Bh), (Ah,Bl).
__global__ __launch_bounds__(256)
void k_mma_gemm(const __half* __restrict__ Ahi, const __half* __restrict__ Alo,
                long aDirStride,
                const __half* __restrict__ Bhi, const __half* __restrict__ Blo,
                long bDirStride,
                float* __restrict__ C, long cDirStride, int ldc, int K, int Ntot,
                const float* __restrict__ resid)
{
    extern __shared__ char dsm[];   // [2][A:16KB | B:16KB] = 64KB
    const int tid = threadIdx.x, w = tid >> 5, lane = tid & 31;
    const int dir = blockIdx.z;
    const int n0 = blockIdx.x * 128, m0 = blockIdx.y * 128;

    Ahi += (size_t)dir * aDirStride;  Alo += (size_t)dir * aDirStride;
    Bhi += (size_t)dir * bDirStride;  Blo += (size_t)dir * bDirStride;
    C   += (size_t)dir * cDirStride;

    const uint32_t sbase = smem_u32(dsm);

    // cp.async per-thread layout: tile = 1024 x 16B lines; 4 lines/thread/operand
    uint32_t sOff[4];
    size_t gOffA[4], gOffB[4];
    #pragma unroll
    for (int j = 0; j < 4; j++) {
        int idx = tid + j*256;
        int row = idx >> 3, c8 = idx & 7;           // c8: 16B chunk (8 halves)
        sOff[j]  = (uint32_t)(row*128 + ((c8 ^ (row & 7)) << 4));
        gOffA[j] = (size_t)(m0 + row)*K + c8*8;
        gOffB[j] = (size_t)(n0 + row)*K + c8*8;
    }

    const int nkc = K / 64;
    const int NCH = 3 * nkc;

    // ldmatrix base addresses (XOR kk<<5 per k16 step)
    const int wm = w >> 2, wn = w & 3;
    const int aRow = wm*64 + (lane & 15);
    const int aSel = (lane >> 4) & 1;
    const int bRow = wn*32 + (lane & 7) + ((lane >> 4) & 1)*8;
    const int bSel = (lane >> 3) & 1;
    uint32_t aBase[4], bBase[2];
    #pragma unroll
    for (int mi = 0; mi < 4; mi++) {
        int r = aRow + mi*16;
        aBase[mi] = (uint32_t)(r*128 + ((aSel ^ (r & 7)) << 4));
    }
    #pragma unroll
    for (int bi = 0; bi < 2; bi++) {
        int r = bRow + bi*16;
        bBase[bi] = (uint32_t)(16384 + r*128 + ((bSel ^ (r & 7)) << 4));
    }

    float acc[4][4][4] = {};

    // issue chunk c's cp.async group
    auto issue = [&](int c) {
        int p = c / nkc, kc = c - p*nkc;
        const __half* As = (p == 1) ? Alo : Ahi;
        const __half* Bs = (p == 2) ? Blo : Bhi;
        size_t k0 = (size_t)kc * 64;
        uint32_t sb = sbase + (uint32_t)(c & 1) * 32768u;
        #pragma unroll
        for (int j = 0; j < 4; j++) CP_ASYNC16(sb + sOff[j],          (const char*)(As + gOffA[j] + k0));
        #pragma unroll
        for (int j = 0; j < 4; j++) CP_ASYNC16(sb + 16384u + sOff[j], (const char*)(Bs + gOffB[j] + k0));
        CP_COMMIT();
    };

    issue(0);
    for (int c = 0; c < NCH; c++) {
        const bool more = (c + 1 < NCH);
        if (more) { issue(c + 1); CP_WAIT1(); } else { CP_WAIT0(); }
        __syncthreads();

        const uint32_t sb = sbase + (uint32_t)(c & 1) * 32768u;
        #pragma unroll
        for (int kk = 0; kk < 4; kk++) {
            const uint32_t kx = (uint32_t)(kk << 5);
            uint32_t a[4][4], b[2][4];
            #pragma unroll
            for (int mi = 0; mi < 4; mi++)
                ldsm4(a[mi][0], a[mi][1], a[mi][2], a[mi][3], (sb + aBase[mi]) ^ kx);
            #pragma unroll
            for (int bi = 0; bi < 2; bi++)
                ldsm4(b[bi][0], b[bi][1], b[bi][2], b[bi][3], (sb + bBase[bi]) ^ kx);
            #pragma unroll
            for (int mi = 0; mi < 4; mi++) {
                #pragma unroll
                for (int nj = 0; nj < 4; nj++)
                    mma16816(acc[mi][nj], a[mi][0], a[mi][1], a[mi][2], a[mi][3],
                             b[nj >> 1][(nj & 1)*2], b[nj >> 1][(nj & 1)*2 + 1]);
            }
        }
        __syncthreads();
    }

    // epilogue: direct STG (float2 per half-frag), optional residual
    const int g = lane >> 2, t = lane & 3;
    #pragma unroll
    for (int mi = 0; mi < 4; mi++) {
        #pragma unroll
        for (int nj = 0; nj < 4; nj++) {
            int cidx = n0 + wn*32 + nj*8 + t*2;
            if (cidx < Ntot) {
                int r = m0 + wm*64 + mi*16 + g;
                size_t o0 = (size_t)r*ldc + cidx;
                size_t o1 = (size_t)(r + 8)*ldc + cidx;
                float2 v0 = make_float2(acc[mi][nj][0], acc[mi][nj][1]);
                float2 v1 = make_float2(acc[mi][nj][2], acc[mi][nj][3]);
                if (resid) {
                    const float2 r0 = *(const float2*)(resid + o0);
                    const float2 r1 = *(const float2*)(resid + o1);
                    v0.x += r0.x; v0.y += r0.y; v1.x += r1.x; v1.y += r1.y;
                }
                *(float2*)(C + o0) = v0;
                *(float2*)(C + o1) = v1;
            }
        }
    }
}

// ================= 3) depthwise conv + bias + SiLU (+ fp16 split out) ========
__global__ void k_conv(const float* __restrict__ cwf, const float* __restrict__ cbf,
                       const float* __restrict__ cwb, const float* __restrict__ cbb)
{
    int d   = blockIdx.x * 256 + threadIdx.x;
    int s0  = blockIdx.y * 64;
    int dir = blockIdx.z >> 1, b = blockIdx.z & 1;
    const float* cw = dir ? cwb : cwf;
    float bias = (dir ? cbb : cbf)[d];
    float w0 = cw[d*4+0], w1 = cw[d*4+1], w2 = cw[d*4+2], w3 = cw[d*4+3];

    const float* xin  = g_xz[dir] + (size_t)b*LSEQ*XZW + d;
    float*       xout = g_xc[dir] + (size_t)b*LSEQ*DI  + d;
    __half* oh = g_axch[dir] + (size_t)b*LSEQ*DI + d;
    __half* ol = g_axcl[dir] + (size_t)b*LSEQ*DI + d;

    if (dir == 0) {
        float xm3 = (s0 >= 3) ? xin[(size_t)(s0-3)*XZW] : 0.f;
        float xm2 = (s0 >= 2) ? xin[(size_t)(s0-2)*XZW] : 0.f;
        float xm1 = (s0 >= 1) ? xin[(size_t)(s0-1)*XZW] : 0.f;
        for (int i = 0; i < 64; i++) {
            int s = s0 + i;
            float x0v = xin[(size_t)s*XZW];
            float v = fmaf(w0, xm3, fmaf(w1, xm2, fmaf(w2, xm1, fmaf(w3, x0v, bias))));
            float sv = silu_(v);
            xout[(size_t)s*DI] = sv;
            split_f16(sv, oh + (size_t)s*DI, ol + (size_t)s*DI);
            xm3 = xm2; xm2 = xm1; xm1 = x0v;
        }
    } else {
        float a0 = xin[(size_t)s0*XZW];
        float a1 = (s0+1 < LSEQ) ? xin[(size_t)(s0+1)*XZW] : 0.f;
        float a2 = (s0+2 < LSEQ) ? xin[(size_t)(s0+2)*XZW] : 0.f;
        for (int i = 0; i < 64; i++) {
            int s = s0 + i;
            float a3 = (s+3 < LSEQ) ? xin[(size_t)(s+3)*XZW] : 0.f;
            float v = fmaf(w3, a0, fmaf(w2, a1, fmaf(w1, a2, fmaf(w0, a3, bias))));
            float sv = silu_(v);
            xout[(size_t)s*DI] = sv;
            split_f16(sv, oh + (size_t)s*DI, ol + (size_t)s*DI);
            a0 = a1; a1 = a2; a2 = a3;
        }
    }
}

// ================= 5) delta: softplus(dt @ dt_w^T + dt_b) (K=48) =============
__global__ void k_delta(const float* __restrict__ dtwf, const float* __restrict__ dtbf,
                        const float* __restrict__ dtwb, const float* __restrict__ dtbb)
{
    int dir = blockIdx.z;
    int d   = blockIdx.x * 256 + threadIdx.x;
    int t0  = blockIdx.y * 16;
    const float* dtw = dir ? dtwb : dtwf;
    float bias = (dir ? dtbb : dtbf)[d];

    float4 w[12];
    const float4* wr = (const float4*)(dtw + (size_t)d*48);
    #pragma unroll
    for (int i = 0; i < 12; i++) w[i] = wr[i];

    __shared__ float4 Ds[16][12];
    if (threadIdx.x < 192) {
        int t = threadIdx.x / 12, q = threadIdx.x % 12;
        Ds[t][q] = *(const float4*)(g_dbc[dir] + (size_t)(t0 + t)*80 + q*4);
    }
    __syncthreads();

    #pragma unroll 4
    for (int t = 0; t < 16; t++) {
        float acc = bias;
        #pragma unroll
        for (int q = 0; q < 12; q++) {
            float4 a = Ds[t][q];
            acc = fmaf(a.x, w[q].x, acc);
            acc = fmaf(a.y, w[q].y, acc);
            acc = fmaf(a.z, w[q].z, acc);
            acc = fmaf(a.w, w[q].w, acc);
        }
        g_delta[dir][(size_t)(t0 + t)*DI + d] = softplus_(acc);
    }
}

// ================= 6) selective scan ========================================
__global__ void k_scan(const float* __restrict__ alf, const float* __restrict__ df,
                       const float* __restrict__ alb, const float* __restrict__ db_)
{
    int dir = blockIdx.z, b = blockIdx.y, d0 = blockIdx.x * 16;
    int tid = threadIdx.x, dl = tid >> 4, n = tid & 15, d = d0 + dl;

    const float* al = dir ? alb : alf;
    float Ad = -__expf(al[(size_t)d*NS + n]);
    float Dd = (dir ? db_ : df)[d];

    const float* pdel = g_delta[dir] + (size_t)b*LSEQ*DI;
    const float* pxc  = g_xc[dir]    + (size_t)b*LSEQ*DI;
    const float* pdbc = g_dbc[dir]   + (size_t)b*LSEQ*80;
    const float* pz   = g_xz[dir]    + (size_t)b*LSEQ*XZW + DI;

    __shared__ float sdel[32][16], sxc[32][16], sB[32][16], sC[32][16], sz[32][16];

    float h = 0.f;
    for (int c = 0; c < LSEQ/32; c++) {
        int base = c * 32;
        #pragma unroll
        for (int idx = tid; idx < 512; idx += 256) {
            int i = idx >> 4, dd = idx & 15;
            int s = dir ? (LSEQ - 1 - (base + i)) : (base + i);
            size_t row = (size_t)s;
            sdel[i][dd] = pdel[row*DI  + d0 + dd];
            sxc [i][dd] = pxc [row*DI  + d0 + dd];
            sz  [i][dd] = pz  [row*XZW + d0 + dd];
            sB  [i][dd] = pdbc[row*80 + 48 + dd];
            sC  [i][dd] = pdbc[row*80 + 64 + dd];
        }
        __syncthreads();
        #pragma unroll 4
        for (int i = 0; i < 32; i++) {
            float dv = sdel[i][dl], xv = sxc[i][dl];
            float e  = __expf(dv * Ad);
            float du = dv * xv;
            h = fmaf(e, h, du * sB[i][n]);
            float p = h * sC[i][n];
            p += __shfl_xor_sync(0xffffffffu, p, 1);
            p += __shfl_xor_sync(0xffffffffu, p, 2);
            p += __shfl_xor_sync(0xffffffffu, p, 4);
            p += __shfl_xor_sync(0xffffffffu, p, 8);
            if (n == 0) {
                int s = dir ? (LSEQ - 1 - (base + i)) : (base + i);
                float zv = sz[i][dl];
                float v = (p + xv*Dd) * silu_(zv);
                size_t o = (size_t)(b*LSEQ + s)*XZW + dir*DI + d;
                split_f16(v, &g_ycath[o], &g_ycatl[o]);
            }
        }
        __syncthreads();
    }
}

// ================= launch ====================================================
extern "C" void kernel_launch(void* const* d_in, const int* in_sizes, int n_in,
                              void* d_out, int out_size)
{
    const float* x    = (const float*)d_in[0];
    const float* ln_g = (const float*)d_in[1];
    const float* ln_b = (const float*)d_in[2];
    const float* f_in_w    = (const float*)d_in[3];
    const float* f_conv_w  = (const float*)d_in[4];
    const float* f_conv_b  = (const float*)d_in[5];
    const float* f_xproj_w = (const float*)d_in[6];
    const float* f_dt_w    = (const float*)d_in[7];
    const float* f_dt_b    = (const float*)d_in[8];
    const float* f_A_log   = (const float*)d_in[9];
    const float* f_D       = (const float*)d_in[10];
    const float* f_out_w   = (const float*)d_in[11];
    const float* b_in_w    = (const float*)d_in[12];
    const float* b_conv_w  = (const float*)d_in[13];
    const float* b_conv_b  = (const float*)d_in[14];
    const float* b_xproj_w = (const float*)d_in[15];
    const float* b_dt_w    = (const float*)d_in[16];
    const float* b_dt_b    = (const float*)d_in[17];
    const float* b_A_log   = (const float*)d_in[18];
    const float* b_D       = (const float*)d_in[19];
    const float* b_out_w   = (const float*)d_in[20];
    float* out = (float*)d_out;

    static const int SMEM_GEMM = 65536;
    cudaFuncSetAttribute(k_mma_gemm, cudaFuncAttributeMaxDynamicSharedMemorySize, SMEM_GEMM);

    float *xz, *dbc;
    __half *a0h, *a0l, *winh, *winl, *wxph, *wxpl, *wouth, *woutl,
           *axch, *axcl, *ych, *ycl;
    cudaGetSymbolAddress((void**)&xz,    g_xz);
    cudaGetSymbolAddress((void**)&dbc,   g_dbc);
    cudaGetSymbolAddress((void**)&a0h,   g_a0h);
    cudaGetSymbolAddress((void**)&a0l,   g_a0l);
    cudaGetSymbolAddress((void**)&winh,  g_winh);
    cudaGetSymbolAddress((void**)&winl,  g_winl);
    cudaGetSymbolAddress((void**)&wxph,  g_wxph);
    cudaGetSymbolAddress((void**)&wxpl,  g_wxpl);
    cudaGetSymbolAddress((void**)&wouth, g_wouth);
    cudaGetSymbolAddress((void**)&woutl, g_woutl);
    cudaGetSymbolAddress((void**)&axch,  g_axch);
    cudaGetSymbolAddress((void**)&axcl,  g_axcl);
    cudaGetSymbolAddress((void**)&ych,   g_ycath);
    cudaGetSymbolAddress((void**)&ycl,   g_ycatl);

    // weight conversions
    k_cvtw_in <<<dim3((XZW*DM + 255)/256, 1, 2), 256>>>(f_in_w, b_in_w);
    k_cvtw_xp <<<dim3((128*DI + 255)/256, 1, 2), 256>>>(f_xproj_w, b_xproj_w);
    k_cvtw_out<<<dim3((DM*XZW + 255)/256, 1, 1), 256>>>(f_out_w, b_out_w);

    // layernorm -> fp16 split
    k_ln<<<NT, 256>>>(x, ln_g, ln_b);

    // in_proj: xz[dir] = x0 @ in_w[dir]^T   (M=2048, N=3072, K=768)
    k_mma_gemm<<<dim3(XZW/128, NT/128, 2), 256, SMEM_GEMM>>>(
        a0h, a0l, 0L,
        winh, winl, (long)XZW*DM,
        xz, (long)NT*XZW, XZW, DM, XZW, nullptr);

    // conv + silu
    k_conv<<<dim3(DI/256, LSEQ/64, 4), 256>>>(f_conv_w, f_conv_b, b_conv_w, b_conv_b);

    // xproj: dbc[dir] = xc[dir] @ xproj_w[dir]^T   (M=2048, N=80(pad128), K=1536)
    k_mma_gemm<<<dim3(1, NT/128, 2), 256, SMEM_GEMM>>>(
        axch, axcl, (long)NT*DI,
        wxph, wxpl, (long)128*DI,
        dbc, (long)NT*80, 80, DI, 80, nullptr);

    // delta
    k_delta<<<dim3(DI/256, NT/16, 2), 256>>>(f_dt_w, f_dt_b, b_dt_w, b_dt_b);

    // selective scan
    k_scan<<<dim3(DI/16, NB, 2), 256>>>(f_A_log, f_D, b_A_log, b_D);

    // out_proj fused both dirs + residual (M=2048, N=768, K=3072)
    k_mma_gemm<<<dim3(DM/128, NT/128, 1), 256, SMEM_GEMM>>>(
        ych, ycl, 0L,
        wouth, woutl, 0L,
        out, 0L, DM, XZW, DM, x);
}

// round 4
// speedup vs baseline: 2.2293x; 1.2910x over previous
#include <cuda_runtime.h>
#include <cuda_fp16.h>
#include <math.h>
#include <stdint.h>

#define DM   768
#define DI   1536
#define NS   16
#define NB   2
#define LSEQ 1024
#define NT   (NB*LSEQ)      // 2048 tokens
#define XZW  (2*DI)         // 3072

// ================= PTX helpers ===============================================
__device__ __forceinline__ uint32_t smem_u32(const void* p) {
    uint32_t a;
    asm("{ .reg .u64 t; cvta.to.shared.u64 t, %1; cvt.u32.u64 %0, t; }" : "=r"(a) : "l"(p));
    return a;
}
#define CP_ASYNC16(dst, src) \
    asm volatile("cp.async.cg.shared.global [%0], [%1], 16;\n" :: "r"(dst), "l"(src))
#define CP_COMMIT() asm volatile("cp.async.commit_group;\n" ::: "memory")
#define CP_WAIT1()  asm volatile("cp.async.wait_group 1;\n" ::: "memory")
#define CP_WAIT0()  asm volatile("cp.async.wait_group 0;\n" ::: "memory")

__device__ __forceinline__ void ldsm4(uint32_t& r0, uint32_t& r1, uint32_t& r2, uint32_t& r3,
                                      uint32_t addr) {
    asm volatile("ldmatrix.sync.aligned.m8n8.x4.shared.b16 {%0,%1,%2,%3}, [%4];\n"
        : "=r"(r0), "=r"(r1), "=r"(r2), "=r"(r3) : "r"(addr));
}
__device__ __forceinline__ void mma16816(float c[4], uint32_t a0, uint32_t a1, uint32_t a2,
                                         uint32_t a3, uint32_t b0, uint32_t b1) {
    asm volatile("mma.sync.aligned.m16n8k16.row.col.f32.f16.f16.f32 "
        "{%0,%1,%2,%3}, {%4,%5,%6,%7}, {%8,%9}, {%0,%1,%2,%3};\n"
        : "+f"(c[0]), "+f"(c[1]), "+f"(c[2]), "+f"(c[3])
        : "r"(a0), "r"(a1), "r"(a2), "r"(a3), "r"(b0), "r"(b1));
}

// ================= scratch (static device memory) ============================
__device__ float g_xz[2][NT*XZW];        // in_proj output per dir (xc | z)
__device__ float g_xc[2][NT*DI];         // conv+silu output per dir (fp32, for scan)
__device__ float g_dbc[2][NT*80];        // xproj output (dt|B|C), split-K accumulated
__device__ float g_delta[2][NT*DI];

// fp16 buffers: activations split hi/lo, weights single fp16
__device__ __align__(256) __half g_a0h[NT*DM],   g_a0l[NT*DM];
__device__ __align__(256) __half g_winh[2][XZW*DM];
__device__ __align__(256) __half g_wxph[2][128*DI];
__device__ __align__(256) __half g_wouth[DM*XZW];                  // concat [768][3072]
__device__ __align__(256) __half g_axch[2][NT*DI],  g_axcl[2][NT*DI];
__device__ __align__(256) __half g_ycath[NT*XZW],   g_ycatl[NT*XZW];

__device__ __forceinline__ float silu_(float v){ return v / (1.f + __expf(-v)); }
__device__ __forceinline__ float softplus_(float v){ return (v > 20.f) ? v : log1pf(__expf(v)); }
__device__ __forceinline__ void split_f16(float v, __half* h, __half* l){
    __half hh = __float2half_rn(v);
    *h = hh;
    *l = __float2half_rn(v - __half2float(hh));
}

// ================= 1) LayerNorm -> fp16 hi/lo ================================
__global__ void k_ln(const float* __restrict__ x, const float* __restrict__ g,
                     const float* __restrict__ b)
{
    int t = blockIdx.x;
    const float* xr = x + (size_t)t*DM;
    float s = 0.f, s2 = 0.f;
    for (int i = threadIdx.x; i < DM; i += 256) { float v = xr[i]; s += v; s2 += v*v; }
    #pragma unroll
    for (int o = 16; o > 0; o >>= 1) {
        s  += __shfl_xor_sync(0xffffffffu, s,  o);
        s2 += __shfl_xor_sync(0xffffffffu, s2, o);
    }
    __shared__ float sh[16];
    int w = threadIdx.x >> 5, l = threadIdx.x & 31;
    if (l == 0) { sh[w] = s; sh[w+8] = s2; }
    __syncthreads();
    float S = 0.f, S2 = 0.f;
    #pragma unroll
    for (int i = 0; i < 8; i++) { S += sh[i]; S2 += sh[i+8]; }
    float mean = S / DM;
    float inv  = rsqrtf(S2 / DM - mean*mean + 1e-5f);
    for (int i = threadIdx.x; i < DM; i += 256) {
        float v = (xr[i] - mean)*inv*g[i] + b[i];
        split_f16(v, &g_a0h[(size_t)t*DM + i], &g_a0l[(size_t)t*DM + i]);
    }
}

// ================= weight conversion (single fp16) ==========================
__global__ void k_cvtw_in(const float* __restrict__ f, const float* __restrict__ b) {
    int dir = blockIdx.z;
    int i = blockIdx.x*256 + threadIdx.x;
    if (i >= XZW*DM) return;
    g_winh[dir][i] = __float2half_rn((dir ? b : f)[i]);
}
__global__ void k_cvtw_xp(const float* __restrict__ f, const float* __restrict__ b) {
    int dir = blockIdx.z;
    int i = blockIdx.x*256 + threadIdx.x;
    if (i >= 128*DI) return;
    int row = i / DI;
    g_wxph[dir][i] = __float2half_rn((row < 80) ? (dir ? b : f)[i] : 0.f);
}
__global__ void k_cvtw_out(const float* __restrict__ f, const float* __restrict__ b) {
    int i = blockIdx.x*256 + threadIdx.x;
    if (i >= DM*XZW) return;
    int n = i / XZW, c = i % XZW;
    g_wouth[i] = __float2half_rn((c < DI) ? f[(size_t)n*DI + c] : b[(size_t)n*DI + c - DI]);
}
__global__ void k_zero_dbc() {
    int i = blockIdx.x*256 + threadIdx.x;
    ((float4*)g_dbc)[i] = make_float4(0.f, 0.f, 0.f, 0.f);   // 2*NT*80/4 = 81920 float4
}

// ================= HMMA GEMM:  C[M,N] (+)= A[M,K] * B[N,K]^T ================
// A = Ah + Al (fp16 split activations), B fp16 weights. 2 MMA products.
// BM=BN=128, BK=64, 3-stage cp.async pipeline (48KB/stage), 8 warps, split-K.
__global__ __launch_bounds__(256, 1)
void k_mma_gemm(const __half* __restrict__ Ahi, const __half* __restrict__ Alo,
                long aDirStride,
                const __half* __restrict__ Bw, long bDirStride,
                float* __restrict__ C, long cDirStride, int ldc, int K, int Ntot,
                int SK)
{
    extern __shared__ char dsm[];      // 3 stages x (Ah 16KB | Al 16KB | Bh 16KB)
    const int tid = threadIdx.x, w = tid >> 5, lane = tid & 31;
    const int dir = blockIdx.z / SK, ks = blockIdx.z % SK;
    const int n0 = blockIdx.x * 128, m0 = blockIdx.y * 128;

    Ahi += (size_t)dir * aDirStride;  Alo += (size_t)dir * aDirStride;
    Bw  += (size_t)dir * bDirStride;
    C   += (size_t)dir * cDirStride;

    const int Kp = K / SK;
    const size_t kBase = (size_t)ks * Kp;
    const int NC = Kp / 64;
    const uint32_t sbase = smem_u32(dsm);

    // cp.async per-thread layout: 4 lines of 16B per tile per thread
    uint32_t sOff[4];
    size_t gOffA[4], gOffB[4];
    #pragma unroll
    for (int j = 0; j < 4; j++) {
        int idx = tid + j*256;
        int row = idx >> 3, c8 = idx & 7;
        sOff[j]  = (uint32_t)(row*128 + ((c8 ^ (row & 7)) << 4));
        gOffA[j] = (size_t)(m0 + row)*K + c8*8 + kBase;
        gOffB[j] = (size_t)(n0 + row)*K + c8*8 + kBase;
    }

    // ldmatrix bases
    const int wm = w >> 2, wn = w & 3;
    const int aRow = wm*64 + (lane & 15);
    const int aSel = (lane >> 4) & 1;
    const int bRow = wn*32 + (lane & 7) + ((lane >> 4) & 1)*8;
    const int bSel = (lane >> 3) & 1;
    uint32_t aBase[4], bBase[2];
    #pragma unroll
    for (int mi = 0; mi < 4; mi++) {
        int r = aRow + mi*16;
        aBase[mi] = (uint32_t)(r*128 + ((aSel ^ (r & 7)) << 4));
    }
    #pragma unroll
    for (int bi = 0; bi < 2; bi++) {
        int r = bRow + bi*16;
        bBase[bi] = (uint32_t)(r*128 + ((bSel ^ (r & 7)) << 4));
    }

    float acc[4][4][4] = {};

    auto issue = [&](int c) {
        uint32_t sb = sbase + (uint32_t)(c % 3) * 49152u;
        size_t k0 = (size_t)c * 64;
        #pragma unroll
        for (int j = 0; j < 4; j++) CP_ASYNC16(sb + sOff[j],           (const char*)(Ahi + gOffA[j] + k0));
        #pragma unroll
        for (int j = 0; j < 4; j++) CP_ASYNC16(sb + 16384u + sOff[j],  (const char*)(Alo + gOffA[j] + k0));
        #pragma unroll
        for (int j = 0; j < 4; j++) CP_ASYNC16(sb + 32768u + sOff[j],  (const char*)(Bw  + gOffB[j] + k0));
        CP_COMMIT();
    };

    issue(0);
    if (NC > 1) issue(1);

    for (int c = 0; c < NC; c++) {
        if (c + 1 < NC) { CP_WAIT1(); } else { CP_WAIT0(); }
        __syncthreads();
        if (c + 2 < NC) issue(c + 2);

        const uint32_t sb = sbase + (uint32_t)(c % 3) * 49152u;
        #pragma unroll
        for (int kk = 0; kk < 4; kk++) {
            const uint32_t kx = (uint32_t)(kk << 5);
            uint32_t a[4][4], al[4][4], b[2][4];
            #pragma unroll
            for (int mi = 0; mi < 4; mi++)
                ldsm4(a[mi][0], a[mi][1], a[mi][2], a[mi][3], (sb + aBase[mi]) ^ kx);
            #pragma unroll
            for (int bi = 0; bi < 2; bi++)
                ldsm4(b[bi][0], b[bi][1], b[bi][2], b[bi][3], (sb + 32768u + bBase[bi]) ^ kx);
            #pragma unroll
            for (int mi = 0; mi < 4; mi++)
                ldsm4(al[mi][0], al[mi][1], al[mi][2], al[mi][3], (sb + 16384u + aBase[mi]) ^ kx);
            #pragma unroll
            for (int mi = 0; mi < 4; mi++)
                #pragma unroll
                for (int nj = 0; nj < 4; nj++)
                    mma16816(acc[mi][nj], a[mi][0], a[mi][1], a[mi][2], a[mi][3],
                             b[nj >> 1][(nj & 1)*2], b[nj >> 1][(nj & 1)*2 + 1]);
            #pragma unroll
            for (int mi = 0; mi < 4; mi++)
                #pragma unroll
                for (int nj = 0; nj < 4; nj++)
                    mma16816(acc[mi][nj], al[mi][0], al[mi][1], al[mi][2], al[mi][3],
                             b[nj >> 1][(nj & 1)*2], b[nj >> 1][(nj & 1)*2 + 1]);
        }
        __syncthreads();
    }

    // epilogue
    const int g = lane >> 2, t = lane & 3;
    #pragma unroll
    for (int mi = 0; mi < 4; mi++) {
        #pragma unroll
        for (int nj = 0; nj < 4; nj++) {
            int cidx = n0 + wn*32 + nj*8 + t*2;
            if (cidx < Ntot) {
                int r = m0 + wm*64 + mi*16 + g;
                size_t o0 = (size_t)r*ldc + cidx;
                size_t o1 = (size_t)(r + 8)*ldc + cidx;
                if (SK > 1) {
                    atomicAdd(C + o0,     acc[mi][nj][0]);
                    atomicAdd(C + o0 + 1, acc[mi][nj][1]);
                    atomicAdd(C + o1,     acc[mi][nj][2]);
                    atomicAdd(C + o1 + 1, acc[mi][nj][3]);
                } else {
                    *(float2*)(C + o0) = make_float2(acc[mi][nj][0], acc[mi][nj][1]);
                    *(float2*)(C + o1) = make_float2(acc[mi][nj][2], acc[mi][nj][3]);
                }
            }
        }
    }
}

// ================= 3) depthwise conv + bias + SiLU ==========================
__global__ void k_conv(const float* __restrict__ cwf, const float* __restrict__ cbf,
                       const float* __restrict__ cwb, const float* __restrict__ cbb)
{
    int d   = blockIdx.x * 256 + threadIdx.x;
    int s0  = blockIdx.y * 64;
    int dir = blockIdx.z >> 1, b = blockIdx.z & 1;
    const float* cw = dir ? cwb : cwf;
    float bias = (dir ? cbb : cbf)[d];
    float w0 = cw[d*4+0], w1 = cw[d*4+1], w2 = cw[d*4+2], w3 = cw[d*4+3];

    const float* xin  = g_xz[dir] + (size_t)b*LSEQ*XZW + d;
    float*       xout = g_xc[dir] + (size_t)b*LSEQ*DI  + d;
    __half* oh = g_axch[dir] + (size_t)b*LSEQ*DI + d;
    __half* ol = g_axcl[dir] + (size_t)b*LSEQ*DI + d;

    if (dir == 0) {
        float xm3 = (s0 >= 3) ? xin[(size_t)(s0-3)*XZW] : 0.f;
        float xm2 = (s0 >= 2) ? xin[(size_t)(s0-2)*XZW] : 0.f;
        float xm1 = (s0 >= 1) ? xin[(size_t)(s0-1)*XZW] : 0.f;
        for (int i = 0; i < 64; i++) {
            int s = s0 + i;
            float x0v = xin[(size_t)s*XZW];
            float v = fmaf(w0, xm3, fmaf(w1, xm2, fmaf(w2, xm1, fmaf(w3, x0v, bias))));
            float sv = silu_(v);
            xout[(size_t)s*DI] = sv;
            split_f16(sv, oh + (size_t)s*DI, ol + (size_t)s*DI);
            xm3 = xm2; xm2 = xm1; xm1 = x0v;
        }
    } else {
        float a0 = xin[(size_t)s0*XZW];
        float a1 = (s0+1 < LSEQ) ? xin[(size_t)(s0+1)*XZW] : 0.f;
        float a2 = (s0+2 < LSEQ) ? xin[(size_t)(s0+2)*XZW] : 0.f;
        for (int i = 0; i < 64; i++) {
            int s = s0 + i;
            float a3 = (s+3 < LSEQ) ? xin[(size_t)(s+3)*XZW] : 0.f;
            float v = fmaf(w3, a0, fmaf(w2, a1, fmaf(w1, a2, fmaf(w0, a3, bias))));
            float sv = silu_(v);
            xout[(size_t)s*DI] = sv;
            split_f16(sv, oh + (size_t)s*DI, ol + (size_t)s*DI);
            a0 = a1; a1 = a2; a2 = a3;
        }
    }
}

// ================= 5) delta: softplus(dt @ dt_w^T + dt_b) (K=48) =============
__global__ void k_delta(const float* __restrict__ dtwf, const float* __restrict__ dtbf,
                        const float* __restrict__ dtwb, const float* __restrict__ dtbb)
{
    int dir = blockIdx.z;
    int d   = blockIdx.x * 256 + threadIdx.x;
    int t0  = blockIdx.y * 16;
    const float* dtw = dir ? dtwb : dtwf;
    float bias = (dir ? dtbb : dtbf)[d];

    float4 w[12];
    const float4* wr = (const float4*)(dtw + (size_t)d*48);
    #pragma unroll
    for (int i = 0; i < 12; i++) w[i] = wr[i];

    __shared__ float4 Ds[16][12];
    if (threadIdx.x < 192) {
        int t = threadIdx.x / 12, q = threadIdx.x % 12;
        Ds[t][q] = *(const float4*)(g_dbc[dir] + (size_t)(t0 + t)*80 + q*4);
    }
    __syncthreads();

    #pragma unroll 4
    for (int t = 0; t < 16; t++) {
        float acc = bias;
        #pragma unroll
        for (int q = 0; q < 12; q++) {
            float4 a = Ds[t][q];
            acc = fmaf(a.x, w[q].x, acc);
            acc = fmaf(a.y, w[q].y, acc);
            acc = fmaf(a.z, w[q].z, acc);
            acc = fmaf(a.w, w[q].w, acc);
        }
        g_delta[dir][(size_t)(t0 + t)*DI + d] = softplus_(acc);
    }
}

// ================= 6) selective scan ========================================
__global__ void k_scan(const float* __restrict__ alf, const float* __restrict__ df,
                       const float* __restrict__ alb, const float* __restrict__ db_)
{
    int dir = blockIdx.z, b = blockIdx.y, d0 = blockIdx.x * 16;
    int tid = threadIdx.x, dl = tid >> 4, n = tid & 15, d = d0 + dl;

    const float* al = dir ? alb : alf;
    float Ad = -__expf(al[(size_t)d*NS + n]);
    float Dd = (dir ? db_ : df)[d];

    const float* pdel = g_delta[dir] + (size_t)b*LSEQ*DI;
    const float* pxc  = g_xc[dir]    + (size_t)b*LSEQ*DI;
    const float* pdbc = g_dbc[dir]   + (size_t)b*LSEQ*80;
    const float* pz   = g_xz[dir]    + (size_t)b*LSEQ*XZW + DI;

    __shared__ float sdel[32][16], sxc[32][16], sB[32][16], sC[32][16], sz[32][16];

    float h = 0.f;
    for (int c = 0; c < LSEQ/32; c++) {
        int base = c * 32;
        #pragma unroll
        for (int idx = tid; idx < 512; idx += 256) {
            int i = idx >> 4, dd = idx & 15;
            int s = dir ? (LSEQ - 1 - (base + i)) : (base + i);
            size_t row = (size_t)s;
            sdel[i][dd] = pdel[row*DI  + d0 + dd];
            sxc [i][dd] = pxc [row*DI  + d0 + dd];
            sz  [i][dd] = pz  [row*XZW + d0 + dd];
            sB  [i][dd] = pdbc[row*80 + 48 + dd];
            sC  [i][dd] = pdbc[row*80 + 64 + dd];
        }
        __syncthreads();
        #pragma unroll 4
        for (int i = 0; i < 32; i++) {
            float dv = sdel[i][dl], xv = sxc[i][dl];
            float e  = __expf(dv * Ad);
            float du = dv * xv;
            h = fmaf(e, h, du * sB[i][n]);
            float p = h * sC[i][n];
            p += __shfl_xor_sync(0xffffffffu, p, 1);
            p += __shfl_xor_sync(0xffffffffu, p, 2);
            p += __shfl_xor_sync(0xffffffffu, p, 4);
            p += __shfl_xor_sync(0xffffffffu, p, 8);
            if (n == 0) {
                int s = dir ? (LSEQ - 1 - (base + i)) : (base + i);
                float zv = sz[i][dl];
                float v = (p + xv*Dd) * silu_(zv);
                size_t o = (size_t)(b*LSEQ + s)*XZW + dir*DI + d;
                split_f16(v, &g_ycath[o], &g_ycatl[o]);
            }
        }
        __syncthreads();
    }
}

// ================= launch ====================================================
extern "C" void kernel_launch(void* const* d_in, const int* in_sizes, int n_in,
                              void* d_out, int out_size)
{
    const float* x    = (const float*)d_in[0];
    const float* ln_g = (const float*)d_in[1];
    const float* ln_b = (const float*)d_in[2];
    const float* f_in_w    = (const float*)d_in[3];
    const float* f_conv_w  = (const float*)d_in[4];
    const float* f_conv_b  = (const float*)d_in[5];
    const float* f_xproj_w = (const float*)d_in[6];
    const float* f_dt_w    = (const float*)d_in[7];
    const float* f_dt_b    = (const float*)d_in[8];
    const float* f_A_log   = (const float*)d_in[9];
    const float* f_D       = (const float*)d_in[10];
    const float* f_out_w   = (const float*)d_in[11];
    const float* b_in_w    = (const float*)d_in[12];
    const float* b_conv_w  = (const float*)d_in[13];
    const float* b_conv_b  = (const float*)d_in[14];
    const float* b_xproj_w = (const float*)d_in[15];
    const float* b_dt_w    = (const float*)d_in[16];
    const float* b_dt_b    = (const float*)d_in[17];
    const float* b_A_log   = (const float*)d_in[18];
    const float* b_D       = (const float*)d_in[19];
    const float* b_out_w   = (const float*)d_in[20];
    float* out = (float*)d_out;

    static const int SMEM_GEMM = 3 * 49152;   // 144KB
    cudaFuncSetAttribute(k_mma_gemm, cudaFuncAttributeMaxDynamicSharedMemorySize, SMEM_GEMM);

    float *xz, *dbc;
    __half *a0h, *a0l, *winh, *wxph, *wouth, *axch, *axcl, *ych, *ycl;
    cudaGetSymbolAddress((void**)&xz,    g_xz);
    cudaGetSymbolAddress((void**)&dbc,   g_dbc);
    cudaGetSymbolAddress((void**)&a0h,   g_a0h);
    cudaGetSymbolAddress((void**)&a0l,   g_a0l);
    cudaGetSymbolAddress((void**)&winh,  g_winh);
    cudaGetSymbolAddress((void**)&wxph,  g_wxph);
    cudaGetSymbolAddress((void**)&wouth, g_wouth);
    cudaGetSymbolAddress((void**)&axch,  g_axch);
    cudaGetSymbolAddress((void**)&axcl,  g_axcl);
    cudaGetSymbolAddress((void**)&ych,   g_ycath);
    cudaGetSymbolAddress((void**)&ycl,   g_ycatl);

    // weight conversions + zero dbc (split-K accumulator)
    k_cvtw_in <<<dim3((XZW*DM + 255)/256, 1, 2), 256>>>(f_in_w, b_in_w);
    k_cvtw_xp <<<dim3((128*DI + 255)/256, 1, 2), 256>>>(f_xproj_w, b_xproj_w);
    k_cvtw_out<<<dim3((DM*XZW + 255)/256, 1, 1), 256>>>(f_out_w, b_out_w);
    k_zero_dbc<<<(2*NT*80/4 + 255)/256, 256>>>();

    // layernorm -> fp16 split
    k_ln<<<NT, 256>>>(x, ln_g, ln_b);

    // in_proj: xz[dir] = x0 @ in_w[dir]^T   (M=2048, N=3072, K=768), SK=1
    k_mma_gemm<<<dim3(XZW/128, NT/128, 2), 256, SMEM_GEMM>>>(
        a0h, a0l, 0L,
        winh, (long)XZW*DM,
        xz, (long)NT*XZW, XZW, DM, XZW, 1);

    // conv + silu
    k_conv<<<dim3(DI/256, LSEQ/64, 4), 256>>>(f_conv_w, f_conv_b, b_conv_w, b_conv_b);

    // xproj: dbc[dir] += xc[dir] @ xproj_w[dir]^T  (M=2048, N=80(pad128), K=1536), SK=4
    k_mma_gemm<<<dim3(1, NT/128, 2*4), 256, SMEM_GEMM>>>(
        axch, axcl, (long)NT*DI,
        wxph, (long)128*DI,
        dbc, (long)NT*80, 80, DI, 80, 4);

    // delta
    k_delta<<<dim3(DI/256, NT/16, 2), 256>>>(f_dt_w, f_dt_b, b_dt_w, b_dt_b);

    // selective scan
    k_scan<<<dim3(DI/16, NB, 2), 256>>>(f_A_log, f_D, b_A_log, b_D);

    // out_proj: out = x + ycat @ woutcat^T  (M=2048, N=768, K=3072), SK=3
    // residual pre-initialized by D2D copy, GEMM accumulates atomically
    cudaMemcpyAsync(out, x, (size_t)NT*DM*sizeof(float), cudaMemcpyDeviceToDevice, 0);
    k_mma_gemm<<<dim3(DM/128, NT/128, 3), 256, SMEM_GEMM>>>(
        ych, ycl, 0L,
        wouth, 0L,
        out, 0L, DM, XZW, DM, 3);
}

// round 5
// speedup vs baseline: 2.7289x; 1.2241x over previous
#include <cuda_runtime.h>
#include <cuda_fp16.h>
#include <math.h>
#include <stdint.h>

#define DM   768
#define DI   1536
#define NS   16
#define NB   2
#define LSEQ 1024
#define NT   (NB*LSEQ)      // 2048 tokens
#define XZW  (2*DI)         // 3072

// ================= PTX helpers ===============================================
__device__ __forceinline__ uint32_t smem_u32(const void* p) {
    uint32_t a;
    asm("{ .reg .u64 t; cvta.to.shared.u64 t, %1; cvt.u32.u64 %0, t; }" : "=r"(a) : "l"(p));
    return a;
}
#define CP_ASYNC16(dst, src) \
    asm volatile("cp.async.cg.shared.global [%0], [%1], 16;\n" :: "r"(dst), "l"(src))
#define CP_COMMIT() asm volatile("cp.async.commit_group;\n" ::: "memory")
#define CP_WAIT1()  asm volatile("cp.async.wait_group 1;\n" ::: "memory")
#define CP_WAIT0()  asm volatile("cp.async.wait_group 0;\n" ::: "memory")

__device__ __forceinline__ void ldsm4(uint32_t& r0, uint32_t& r1, uint32_t& r2, uint32_t& r3,
                                      uint32_t addr) {
    asm volatile("ldmatrix.sync.aligned.m8n8.x4.shared.b16 {%0,%1,%2,%3}, [%4];\n"
        : "=r"(r0), "=r"(r1), "=r"(r2), "=r"(r3) : "r"(addr));
}
__device__ __forceinline__ void mma16816(float c[4], uint32_t a0, uint32_t a1, uint32_t a2,
                                         uint32_t a3, uint32_t b0, uint32_t b1) {
    asm volatile("mma.sync.aligned.m16n8k16.row.col.f32.f16.f16.f32 "
        "{%0,%1,%2,%3}, {%4,%5,%6,%7}, {%8,%9}, {%0,%1,%2,%3};\n"
        : "+f"(c[0]), "+f"(c[1]), "+f"(c[2]), "+f"(c[3])
        : "r"(a0), "r"(a1), "r"(a2), "r"(a3), "r"(b0), "r"(b1));
}

// ================= scratch (static device memory) ============================
__device__ float g_xz[2][NT*XZW];        // in_proj output per dir (xc | z)
__device__ float g_xc[2][NT*DI];         // conv+silu output per dir (fp32, for scan)
__device__ float g_dbc[2][NT*80];        // xproj output (dt|B|C), split-K accumulated
__device__ float g_delta[2][NT*DI];

// fp16 buffers (single precision-level, per R4 attenuation calibration)
__device__ __align__(256) __half g_a0h[NT*DM];
__device__ __align__(256) __half g_winh[2][XZW*DM];
__device__ __align__(256) __half g_wxph[2][128*DI];
__device__ __align__(256) __half g_wouth[DM*XZW];                  // concat [768][3072]
__device__ __align__(256) __half g_axch[2][NT*DI];
__device__ __align__(256) __half g_ycath[NT*XZW];

__device__ __forceinline__ float silu_(float v){ return v / (1.f + __expf(-v)); }
__device__ __forceinline__ float softplus_(float v){ return (v > 20.f) ? v : log1pf(__expf(v)); }

// ================= 1) LayerNorm -> fp16 ======================================
__global__ void k_ln(const float* __restrict__ x, const float* __restrict__ g,
                     const float* __restrict__ b)
{
    int t = blockIdx.x;
    const float* xr = x + (size_t)t*DM;
    float s = 0.f, s2 = 0.f;
    for (int i = threadIdx.x; i < DM; i += 256) { float v = xr[i]; s += v; s2 += v*v; }
    #pragma unroll
    for (int o = 16; o > 0; o >>= 1) {
        s  += __shfl_xor_sync(0xffffffffu, s,  o);
        s2 += __shfl_xor_sync(0xffffffffu, s2, o);
    }
    __shared__ float sh[16];
    int w = threadIdx.x >> 5, l = threadIdx.x & 31;
    if (l == 0) { sh[w] = s; sh[w+8] = s2; }
    __syncthreads();
    float S = 0.f, S2 = 0.f;
    #pragma unroll
    for (int i = 0; i < 8; i++) { S += sh[i]; S2 += sh[i+8]; }
    float mean = S / DM;
    float inv  = rsqrtf(S2 / DM - mean*mean + 1e-5f);
    for (int i = threadIdx.x; i < DM; i += 256) {
        float v = (xr[i] - mean)*inv*g[i] + b[i];
        g_a0h[(size_t)t*DM + i] = __float2half_rn(v);
    }
}

// ================= weight conversion (fp16) =================================
__global__ void k_cvtw_in(const float* __restrict__ f, const float* __restrict__ b) {
    int dir = blockIdx.z;
    int i = blockIdx.x*256 + threadIdx.x;
    if (i >= XZW*DM) return;
    g_winh[dir][i] = __float2half_rn((dir ? b : f)[i]);
}
__global__ void k_cvtw_xp(const float* __restrict__ f, const float* __restrict__ b) {
    int dir = blockIdx.z;
    int i = blockIdx.x*256 + threadIdx.x;
    if (i >= 128*DI) return;
    int row = i / DI;
    g_wxph[dir][i] = __float2half_rn((row < 80) ? (dir ? b : f)[i] : 0.f);
}
__global__ void k_cvtw_out(const float* __restrict__ f, const float* __restrict__ b) {
    int i = blockIdx.x*256 + threadIdx.x;
    if (i >= DM*XZW) return;
    int n = i / XZW, c = i % XZW;
    g_wouth[i] = __float2half_rn((c < DI) ? f[(size_t)n*DI + c] : b[(size_t)n*DI + c - DI]);
}
__global__ void k_zero_dbc() {
    int i = blockIdx.x*256 + threadIdx.x;
    ((float4*)g_dbc)[i] = make_float4(0.f, 0.f, 0.f, 0.f);   // 2*NT*80/4 = 81920 float4
}

// ================= HMMA GEMM:  C[M,N] (+)= A[M,K] * B[N,K]^T (fp16) =========
// BM=BN=128, BK=64, 3-stage cp.async pipeline (32KB/stage), 8 warps, 2 CTAs/SM.
__global__ __launch_bounds__(256, 2)
void k_mma_gemm(const __half* __restrict__ Ah, long aDirStride,
                const __half* __restrict__ Bw, long bDirStride,
                float* __restrict__ C, long cDirStride, int ldc, int K, int Ntot,
                int SK)
{
    extern __shared__ char dsm[];      // 3 stages x (A 16KB | B 16KB)
    const int tid = threadIdx.x, w = tid >> 5, lane = tid & 31;
    const int dir = blockIdx.z / SK, ks = blockIdx.z % SK;
    const int n0 = blockIdx.x * 128, m0 = blockIdx.y * 128;

    Ah += (size_t)dir * aDirStride;
    Bw += (size_t)dir * bDirStride;
    C  += (size_t)dir * cDirStride;

    const int Kp = K / SK;
    const size_t kBase = (size_t)ks * Kp;
    const int NC = Kp / 64;
    const uint32_t sbase = smem_u32(dsm);

    // cp.async per-thread layout: 4 lines of 16B per tile per thread
    uint32_t sOff[4];
    size_t gOffA[4], gOffB[4];
    #pragma unroll
    for (int j = 0; j < 4; j++) {
        int idx = tid + j*256;
        int row = idx >> 3, c8 = idx & 7;
        sOff[j]  = (uint32_t)(row*128 + ((c8 ^ (row & 7)) << 4));
        gOffA[j] = (size_t)(m0 + row)*K + c8*8 + kBase;
        gOffB[j] = (size_t)(n0 + row)*K + c8*8 + kBase;
    }

    // ldmatrix bases
    const int wm = w >> 2, wn = w & 3;
    const int aRow = wm*64 + (lane & 15);
    const int aSel = (lane >> 4) & 1;
    const int bRow = wn*32 + (lane & 7) + ((lane >> 4) & 1)*8;
    const int bSel = (lane >> 3) & 1;
    uint32_t aBase[4], bBase[2];
    #pragma unroll
    for (int mi = 0; mi < 4; mi++) {
        int r = aRow + mi*16;
        aBase[mi] = (uint32_t)(r*128 + ((aSel ^ (r & 7)) << 4));
    }
    #pragma unroll
    for (int bi = 0; bi < 2; bi++) {
        int r = bRow + bi*16;
        bBase[bi] = (uint32_t)(16384 + r*128 + ((bSel ^ (r & 7)) << 4));
    }

    float acc[4][4][4] = {};

    auto issue = [&](int c) {
        uint32_t sb = sbase + (uint32_t)(c % 3) * 32768u;
        size_t k0 = (size_t)c * 64;
        #pragma unroll
        for (int j = 0; j < 4; j++) CP_ASYNC16(sb + sOff[j],           (const char*)(Ah + gOffA[j] + k0));
        #pragma unroll
        for (int j = 0; j < 4; j++) CP_ASYNC16(sb + 16384u + sOff[j],  (const char*)(Bw + gOffB[j] + k0));
        CP_COMMIT();
    };

    issue(0);
    if (NC > 1) issue(1);

    for (int c = 0; c < NC; c++) {
        if (c + 1 < NC) { CP_WAIT1(); } else { CP_WAIT0(); }
        __syncthreads();
        if (c + 2 < NC) issue(c + 2);

        const uint32_t sb = sbase + (uint32_t)(c % 3) * 32768u;
        #pragma unroll
        for (int kk = 0; kk < 4; kk++) {
            const uint32_t kx = (uint32_t)(kk << 5);
            uint32_t a[4][4], b[2][4];
            #pragma unroll
            for (int mi = 0; mi < 4; mi++)
                ldsm4(a[mi][0], a[mi][1], a[mi][2], a[mi][3], (sb + aBase[mi]) ^ kx);
            #pragma unroll
            for (int bi = 0; bi < 2; bi++)
                ldsm4(b[bi][0], b[bi][1], b[bi][2], b[bi][3], (sb + bBase[bi]) ^ kx);
            #pragma unroll
            for (int mi = 0; mi < 4; mi++)
                #pragma unroll
                for (int nj = 0; nj < 4; nj++)
                    mma16816(acc[mi][nj], a[mi][0], a[mi][1], a[mi][2], a[mi][3],
                             b[nj >> 1][(nj & 1)*2], b[nj >> 1][(nj & 1)*2 + 1]);
        }
        __syncthreads();
    }

    // epilogue
    const int g = lane >> 2, t = lane & 3;
    #pragma unroll
    for (int mi = 0; mi < 4; mi++) {
        #pragma unroll
        for (int nj = 0; nj < 4; nj++) {
            int cidx = n0 + wn*32 + nj*8 + t*2;
            if (cidx < Ntot) {
                int r = m0 + wm*64 + mi*16 + g;
                size_t o0 = (size_t)r*ldc + cidx;
                size_t o1 = (size_t)(r + 8)*ldc + cidx;
                if (SK > 1) {
                    atomicAdd(C + o0,     acc[mi][nj][0]);
                    atomicAdd(C + o0 + 1, acc[mi][nj][1]);
                    atomicAdd(C + o1,     acc[mi][nj][2]);
                    atomicAdd(C + o1 + 1, acc[mi][nj][3]);
                } else {
                    *(float2*)(C + o0) = make_float2(acc[mi][nj][0], acc[mi][nj][1]);
                    *(float2*)(C + o1) = make_float2(acc[mi][nj][2], acc[mi][nj][3]);
                }
            }
        }
    }
}

// ================= 3) depthwise conv + bias + SiLU ==========================
__global__ void k_conv(const float* __restrict__ cwf, const float* __restrict__ cbf,
                       const float* __restrict__ cwb, const float* __restrict__ cbb)
{
    int d   = blockIdx.x * 256 + threadIdx.x;
    int s0  = blockIdx.y * 64;
    int dir = blockIdx.z >> 1, b = blockIdx.z & 1;
    const float* cw = dir ? cwb : cwf;
    float bias = (dir ? cbb : cbf)[d];
    float w0 = cw[d*4+0], w1 = cw[d*4+1], w2 = cw[d*4+2], w3 = cw[d*4+3];

    const float* xin  = g_xz[dir] + (size_t)b*LSEQ*XZW + d;
    float*       xout = g_xc[dir] + (size_t)b*LSEQ*DI  + d;
    __half* oh = g_axch[dir] + (size_t)b*LSEQ*DI + d;

    if (dir == 0) {
        float xm3 = (s0 >= 3) ? xin[(size_t)(s0-3)*XZW] : 0.f;
        float xm2 = (s0 >= 2) ? xin[(size_t)(s0-2)*XZW] : 0.f;
        float xm1 = (s0 >= 1) ? xin[(size_t)(s0-1)*XZW] : 0.f;
        for (int i = 0; i < 64; i++) {
            int s = s0 + i;
            float x0v = xin[(size_t)s*XZW];
            float v = fmaf(w0, xm3, fmaf(w1, xm2, fmaf(w2, xm1, fmaf(w3, x0v, bias))));
            float sv = silu_(v);
            xout[(size_t)s*DI] = sv;
            oh[(size_t)s*DI] = __float2half_rn(sv);
            xm3 = xm2; xm2 = xm1; xm1 = x0v;
        }
    } else {
        float a0 = xin[(size_t)s0*XZW];
        float a1 = (s0+1 < LSEQ) ? xin[(size_t)(s0+1)*XZW] : 0.f;
        float a2 = (s0+2 < LSEQ) ? xin[(size_t)(s0+2)*XZW] : 0.f;
        for (int i = 0; i < 64; i++) {
            int s = s0 + i;
            float a3 = (s+3 < LSEQ) ? xin[(size_t)(s+3)*XZW] : 0.f;
            float v = fmaf(w3, a0, fmaf(w2, a1, fmaf(w1, a2, fmaf(w0, a3, bias))));
            float sv = silu_(v);
            xout[(size_t)s*DI] = sv;
            oh[(size_t)s*DI] = __float2half_rn(sv);
            a0 = a1; a1 = a2; a2 = a3;
        }
    }
}

// ================= 5) delta: softplus(dt @ dt_w^T + dt_b) (K=48) =============
__global__ void k_delta(const float* __restrict__ dtwf, const float* __restrict__ dtbf,
                        const float* __restrict__ dtwb, const float* __restrict__ dtbb)
{
    int dir = blockIdx.z;
    int d   = blockIdx.x * 256 + threadIdx.x;
    int t0  = blockIdx.y * 16;
    const float* dtw = dir ? dtwb : dtwf;
    float bias = (dir ? dtbb : dtbf)[d];

    float4 w[12];
    const float4* wr = (const float4*)(dtw + (size_t)d*48);
    #pragma unroll
    for (int i = 0; i < 12; i++) w[i] = wr[i];

    __shared__ float4 Ds[16][12];
    if (threadIdx.x < 192) {
        int t = threadIdx.x / 12, q = threadIdx.x % 12;
        Ds[t][q] = *(const float4*)(g_dbc[dir] + (size_t)(t0 + t)*80 + q*4);
    }
    __syncthreads();

    #pragma unroll 4
    for (int t = 0; t < 16; t++) {
        float acc = bias;
        #pragma unroll
        for (int q = 0; q < 12; q++) {
            float4 a = Ds[t][q];
            acc = fmaf(a.x, w[q].x, acc);
            acc = fmaf(a.y, w[q].y, acc);
            acc = fmaf(a.z, w[q].z, acc);
            acc = fmaf(a.w, w[q].w, acc);
        }
        g_delta[dir][(size_t)(t0 + t)*DI + d] = softplus_(acc);
    }
}

// ================= 6) selective scan ========================================
__global__ void k_scan(const float* __restrict__ alf, const float* __restrict__ df,
                       const float* __restrict__ alb, const float* __restrict__ db_)
{
    int dir = blockIdx.z, b = blockIdx.y, d0 = blockIdx.x * 16;
    int tid = threadIdx.x, dl = tid >> 4, n = tid & 15, d = d0 + dl;

    const float* al = dir ? alb : alf;
    float Ad = -__expf(al[(size_t)d*NS + n]);
    float Dd = (dir ? db_ : df)[d];

    const float* pdel = g_delta[dir] + (size_t)b*LSEQ*DI;
    const float* pxc  = g_xc[dir]    + (size_t)b*LSEQ*DI;
    const float* pdbc = g_dbc[dir]   + (size_t)b*LSEQ*80;
    const float* pz   = g_xz[dir]    + (size_t)b*LSEQ*XZW + DI;

    __shared__ float sdel[32][16], sxc[32][16], sB[32][16], sC[32][16], sz[32][16];

    float h = 0.f;
    for (int c = 0; c < LSEQ/32; c++) {
        int base = c * 32;
        #pragma unroll
        for (int idx = tid; idx < 512; idx += 256) {
            int i = idx >> 4, dd = idx & 15;
            int s = dir ? (LSEQ - 1 - (base + i)) : (base + i);
            size_t row = (size_t)s;
            sdel[i][dd] = pdel[row*DI  + d0 + dd];
            sxc [i][dd] = pxc [row*DI  + d0 + dd];
            sz  [i][dd] = pz  [row*XZW + d0 + dd];
            sB  [i][dd] = pdbc[row*80 + 48 + dd];
            sC  [i][dd] = pdbc[row*80 + 64 + dd];
        }
        __syncthreads();
        #pragma unroll 4
        for (int i = 0; i < 32; i++) {
            float dv = sdel[i][dl], xv = sxc[i][dl];
            float e  = __expf(dv * Ad);
            float du = dv * xv;
            h = fmaf(e, h, du * sB[i][n]);
            float p = h * sC[i][n];
            p += __shfl_xor_sync(0xffffffffu, p, 1);
            p += __shfl_xor_sync(0xffffffffu, p, 2);
            p += __shfl_xor_sync(0xffffffffu, p, 4);
            p += __shfl_xor_sync(0xffffffffu, p, 8);
            if (n == 0) {
                int s = dir ? (LSEQ - 1 - (base + i)) : (base + i);
                float zv = sz[i][dl];
                float v = (p + xv*Dd) * silu_(zv);
                size_t o = (size_t)(b*LSEQ + s)*XZW + dir*DI + d;
                g_ycath[o] = __float2half_rn(v);
            }
        }
        __syncthreads();
    }
}

// ================= launch ====================================================
extern "C" void kernel_launch(void* const* d_in, const int* in_sizes, int n_in,
                              void* d_out, int out_size)
{
    const float* x    = (const float*)d_in[0];
    const float* ln_g = (const float*)d_in[1];
    const float* ln_b = (const float*)d_in[2];
    const float* f_in_w    = (const float*)d_in[3];
    const float* f_conv_w  = (const float*)d_in[4];
    const float* f_conv_b  = (const float*)d_in[5];
    const float* f_xproj_w = (const float*)d_in[6];
    const float* f_dt_w    = (const float*)d_in[7];
    const float* f_dt_b    = (const float*)d_in[8];
    const float* f_A_log   = (const float*)d_in[9];
    const float* f_D       = (const float*)d_in[10];
    const float* f_out_w   = (const float*)d_in[11];
    const float* b_in_w    = (const float*)d_in[12];
    const float* b_conv_w  = (const float*)d_in[13];
    const float* b_conv_b  = (const float*)d_in[14];
    const float* b_xproj_w = (const float*)d_in[15];
    const float* b_dt_w    = (const float*)d_in[16];
    const float* b_dt_b    = (const float*)d_in[17];
    const float* b_A_log   = (const float*)d_in[18];
    const float* b_D       = (const float*)d_in[19];
    const float* b_out_w   = (const float*)d_in[20];
    float* out = (float*)d_out;

    static const int SMEM_GEMM = 3 * 32768;   // 96KB -> 2 CTAs/SM
    cudaFuncSetAttribute(k_mma_gemm, cudaFuncAttributeMaxDynamicSharedMemorySize, SMEM_GEMM);

    float *xz, *dbc;
    __half *a0h, *winh, *wxph, *wouth, *axch, *ych;
    cudaGetSymbolAddress((void**)&xz,    g_xz);
    cudaGetSymbolAddress((void**)&dbc,   g_dbc);
    cudaGetSymbolAddress((void**)&a0h,   g_a0h);
    cudaGetSymbolAddress((void**)&winh,  g_winh);
    cudaGetSymbolAddress((void**)&wxph,  g_wxph);
    cudaGetSymbolAddress((void**)&wouth, g_wouth);
    cudaGetSymbolAddress((void**)&axch,  g_axch);
    cudaGetSymbolAddress((void**)&ych,   g_ycath);

    // weight conversions + zero dbc (split-K accumulator)
    k_cvtw_in <<<dim3((XZW*DM + 255)/256, 1, 2), 256>>>(f_in_w, b_in_w);
    k_cvtw_xp <<<dim3((128*DI + 255)/256, 1, 2), 256>>>(f_xproj_w, b_xproj_w);
    k_cvtw_out<<<dim3((DM*XZW + 255)/256, 1, 1), 256>>>(f_out_w, b_out_w);
    k_zero_dbc<<<(2*NT*80/4 + 255)/256, 256>>>();

    // layernorm -> fp16
    k_ln<<<NT, 256>>>(x, ln_g, ln_b);

    // in_proj: xz[dir] = x0 @ in_w[dir]^T   (M=2048, N=3072, K=768), SK=1
    k_mma_gemm<<<dim3(XZW/128, NT/128, 2), 256, SMEM_GEMM>>>(
        a0h, 0L,
        winh, (long)XZW*DM,
        xz, (long)NT*XZW, XZW, DM, XZW, 1);

    // conv + silu
    k_conv<<<dim3(DI/256, LSEQ/64, 4), 256>>>(f_conv_w, f_conv_b, b_conv_w, b_conv_b);

    // xproj: dbc[dir] += xc[dir] @ xproj_w[dir]^T  (M=2048, N=80(pad128), K=1536), SK=4
    k_mma_gemm<<<dim3(1, NT/128, 2*4), 256, SMEM_GEMM>>>(
        axch, (long)NT*DI,
        wxph, (long)128*DI,
        dbc, (long)NT*80, 80, DI, 80, 4);

    // delta
    k_delta<<<dim3(DI/256, NT/16, 2), 256>>>(f_dt_w, f_dt_b, b_dt_w, b_dt_b);

    // selective scan
    k_scan<<<dim3(DI/16, NB, 2), 256>>>(f_A_log, f_D, b_A_log, b_D);

    // out_proj: out = x + ycat @ woutcat^T  (M=2048, N=768, K=3072), SK=3
    cudaMemcpyAsync(out, x, (size_t)NT*DM*sizeof(float), cudaMemcpyDeviceToDevice, 0);
    k_mma_gemm<<<dim3(DM/128, NT/128, 3), 256, SMEM_GEMM>>>(
        ych, 0L,
        wouth, 0L,
        out, 0L, DM, XZW, DM, 3);
}